// round 2
// baseline (speedup 1.0000x reference)
#include <cuda_runtime.h>
#include <cuda_bf16.h>
#include <cstdint>

// Sparse 3x3x3 conv block, 2 layers, N=64 channels, D=128 grid.
// Exploit ~4.8% voxel occupancy: build per-offset (out,in) pair lists
// (~2.25 valid taps/point), then dense 128-pair x 64x64 gather-GEMM-scatter
// tiles, W_k in SMEM, fp32 atomics into bias-initialized accumulator.
// kernel_launch contains ONLY kernel launches (graph-capture safe).

#define DG   128
#define NCH  64
#define MAXM 131072
#define NOFF 27

__device__ int   g_lookup[DG * DG * DG];     // voxel -> point index (-1 empty)
__device__ int   g_cnt[NOFF];                // pairs per offset
__device__ int   g_pout[NOFF * MAXM];        // output point index per pair
__device__ int   g_pin [NOFF * MAXM];        // input (gather) point index per pair
__device__ float g_h   [MAXM * NCH];         // hidden activations (layer 1 out)

// ---------------------------------------------------------------------------
__global__ void k_fill(int total) {
    int i = blockIdx.x * blockDim.x + threadIdx.x;
    if (i < total) g_lookup[i] = -1;
    if (i < NOFF)  g_cnt[i] = 0;
}

__global__ void k_scatter(const int* __restrict__ coords, int M) {
    int i = blockIdx.x * blockDim.x + threadIdx.x;
    if (i >= M) return;
    int x = coords[3 * i + 0];
    int y = coords[3 * i + 1];
    int z = coords[3 * i + 2];
    g_lookup[(x * DG + y) * DG + z] = i;
}

// Build per-offset pair lists with warp-aggregated reservation (1 ATOMG per
// warp per offset instead of 1 per pair).
__global__ void k_pairs(const int* __restrict__ coords, int M) {
    int i    = blockIdx.x * blockDim.x + threadIdx.x;
    int lane = threadIdx.x & 31;
    bool act = (i < M);
    int cx = 0, cy = 0, cz = 0;
    if (act) {
        cx = coords[3 * i + 0];
        cy = coords[3 * i + 1];
        cz = coords[3 * i + 2];
    }
    for (int k = 0; k < NOFF; k++) {
        int dx = k / 9 - 1, dy = (k / 3) % 3 - 1, dz = k % 3 - 1;
        int nidx = -1;
        if (act) {
            int nx = cx + dx, ny = cy + dy, nz = cz + dz;
            if (nx >= 0 && nx < DG && ny >= 0 && ny < DG && nz >= 0 && nz < DG)
                nidx = g_lookup[(nx * DG + ny) * DG + nz];
        }
        bool valid = (nidx >= 0);
        unsigned m = __ballot_sync(0xffffffffu, valid);
        if (!m) continue;
        int total  = __popc(m);
        int leader = __ffs(m) - 1;
        int base = 0;
        if (lane == leader) base = atomicAdd(&g_cnt[k], total);
        base = __shfl_sync(0xffffffffu, base, leader);
        if (valid) {
            int pos = k * MAXM + base + __popc(m & ((1u << lane) - 1));
            g_pout[pos] = i;
            g_pin [pos] = nidx;
        }
    }
}

// dst[i*64 + c] = bias[c]   (dst==nullptr -> g_h)
__global__ void k_bias(float* dst, const float* __restrict__ b, int n) {
    float* out = dst ? dst : g_h;
    int i = blockIdx.x * blockDim.x + threadIdx.x;
    if (i < n) out[i] = b[i & (NCH - 1)];
}

__global__ void k_relu(float* dst, int n) {
    float* x = dst ? dst : g_h;
    int i = blockIdx.x * blockDim.x + threadIdx.x;
    if (i < n) x[i] = fmaxf(x[i], 0.0f);
}

// ---------------------------------------------------------------------------
// One block = 128 pairs of a single offset k. 128 threads.
// SMEM: W_k [64x64] (16KB) + gathered tile transposed GT[j=64][p=128] (32KB).
// Each thread computes an 8-point x 8-channel register tile (64 accs).
// Scatter-add via fp32 global atomics (races only across offsets).
// xin==nullptr -> input is g_h; outp==nullptr -> output is g_h.
__global__ void __launch_bounds__(128) k_conv(const float* xin,
                                              const float* __restrict__ W,
                                              float* outp) {
    extern __shared__ float sm[];
    float* sW  = sm;               // 4096 floats
    float* sGT = sm + 4096;        // 64*128 floats, j-major

    const float* x  = xin  ? xin  : (const float*)g_h;
    float* out      = outp ? outp : g_h;

    int k    = blockIdx.y;
    int cnt  = g_cnt[k];
    int base = blockIdx.x * 128;
    if (base >= cnt) return;

    int tx = threadIdx.x;

    // Stage W_k (4096 floats = 1024 float4; 8 per thread)
    const float4* Wk4 = (const float4*)(W + k * (NCH * NCH));
    float4* sW4 = (float4*)sW;
#pragma unroll
    for (int t = 0; t < 8; t++) sW4[tx + t * 128] = Wk4[tx + t * 128];

    // Gather one input row per thread, transposed into sGT[j][p]
    int p = tx;
    int gidx = -1;
    if (base + p < cnt) gidx = g_pin[k * MAXM + base + p];
    if (gidx >= 0) {
        const float4* row = (const float4*)(x + (size_t)gidx * NCH);
#pragma unroll
        for (int q = 0; q < 16; q++) {
            float4 v = row[q];
            sGT[(4 * q + 0) * 128 + p] = v.x;
            sGT[(4 * q + 1) * 128 + p] = v.y;
            sGT[(4 * q + 2) * 128 + p] = v.z;
            sGT[(4 * q + 3) * 128 + p] = v.w;
        }
    } else {
#pragma unroll
        for (int j = 0; j < NCH; j++) sGT[j * 128 + p] = 0.0f;
    }
    __syncthreads();

    int cg = tx & 7;        // channel group: channels cg*8 .. cg*8+7
    int pg = tx >> 3;       // point group:   pairs    pg*8 .. pg*8+7

    float acc[8][8];
#pragma unroll
    for (int a = 0; a < 8; a++)
#pragma unroll
        for (int b = 0; b < 8; b++) acc[a][b] = 0.0f;

#pragma unroll 8
    for (int j = 0; j < NCH; j++) {
        float4 a0 = *(const float4*)&sGT[j * 128 + pg * 8];
        float4 a1 = *(const float4*)&sGT[j * 128 + pg * 8 + 4];
        float4 b0 = *(const float4*)&sW[j * NCH + cg * 8];
        float4 b1 = *(const float4*)&sW[j * NCH + cg * 8 + 4];
        float av[8] = {a0.x, a0.y, a0.z, a0.w, a1.x, a1.y, a1.z, a1.w};
        float bv[8] = {b0.x, b0.y, b0.z, b0.w, b1.x, b1.y, b1.z, b1.w};
#pragma unroll
        for (int pp = 0; pp < 8; pp++)
#pragma unroll
            for (int cc = 0; cc < 8; cc++)
                acc[pp][cc] = fmaf(av[pp], bv[cc], acc[pp][cc]);
    }

    // Scatter-add
#pragma unroll
    for (int pp = 0; pp < 8; pp++) {
        int pairidx = base + pg * 8 + pp;
        if (pairidx < cnt) {
            int row = g_pout[k * MAXM + pairidx];
            float* o = out + (size_t)row * NCH + cg * 8;
#pragma unroll
            for (int cc = 0; cc < 8; cc++) atomicAdd(o + cc, acc[pp][cc]);
        }
    }
}

// ---------------------------------------------------------------------------
extern "C" void kernel_launch(void* const* d_in, const int* in_sizes, int n_in,
                              void* d_out, int out_size) {
    const float* feats  = (const float*)d_in[0];
    const float* W1     = (const float*)d_in[1];
    const float* b1     = (const float*)d_in[2];
    const float* W2     = (const float*)d_in[3];
    const float* b2     = (const float*)d_in[4];
    const int*   coords = (const int*)d_in[5];
    int M = in_sizes[0] / NCH;
    float* out = (float*)d_out;

    const int smem = (4096 + NCH * 128) * (int)sizeof(float);  // 49152 B (<= default)

    int vox = DG * DG * DG;
    k_fill<<<(vox + 255) / 256, 256>>>(vox);
    k_scatter<<<(M + 255) / 256, 256>>>(coords, M);
    k_pairs<<<(M + 255) / 256, 256>>>(coords, M);

    int tiles = (M + 127) / 128;
    dim3 cgrid(tiles, NOFF);
    int nelem = M * NCH;

    // Layer 1: h = relu(conv(feats, W1) + b1)   (h == g_h via nullptr)
    k_bias<<<(nelem + 255) / 256, 256>>>(nullptr, b1, nelem);
    k_conv<<<cgrid, 128, smem>>>(feats, W1, nullptr);
    k_relu<<<(nelem + 255) / 256, 256>>>(nullptr, nelem);

    // Layer 2: out = relu(conv(h, W2) + b2)
    k_bias<<<(nelem + 255) / 256, 256>>>(out, b2, nelem);
    k_conv<<<cgrid, 128, smem>>>(nullptr, W2, out);
    k_relu<<<(nelem + 255) / 256, 256>>>(out, nelem);
}

// round 6
// speedup vs baseline: 1.5050x; 1.5050x over previous
#include <cuda_runtime.h>
#include <cuda_bf16.h>
#include <cstdint>

// Sparse 3x3x3 conv block, 2 layers, N=64 channels, D=128 grid.
// Per-offset pair lists (~2.25 valid taps/point at 4.8% occupancy), then
// 128-pair x 64x64 gather-GEMM-scatter tiles. GEMM inner loop uses packed
// fma.rn.f32x2 (FFMA2, 2x fp32 rate). Scatter via red.global.add.v4.f32.
// Layer-1 ReLU fused into layer-2 gather; bias inits fused+vectorized.
// All device scratch arrays explicitly 16B-aligned for v4 accesses.

#define DG   128
#define NCH  64
#define MAXM 131072
#define NOFF 27

__device__ __align__(16) int   g_lookup[DG * DG * DG];
__device__ __align__(16) int   g_cnt[NOFF];
__device__ __align__(16) int   g_pout[NOFF * MAXM];
__device__ __align__(16) int   g_pin [NOFF * MAXM];
__device__ __align__(16) float g_h   [MAXM * NCH];

// ---------------------------------------------------------------------------
__global__ void k_fill(int nquad) {
    int i = blockIdx.x * blockDim.x + threadIdx.x;
    if (i < nquad) ((int4*)g_lookup)[i] = make_int4(-1, -1, -1, -1);
    if (i < NOFF)  g_cnt[i] = 0;
}

__global__ void k_scatter(const int* __restrict__ coords, int M) {
    int i = blockIdx.x * blockDim.x + threadIdx.x;
    if (i >= M) return;
    int x = coords[3 * i + 0];
    int y = coords[3 * i + 1];
    int z = coords[3 * i + 2];
    g_lookup[(x * DG + y) * DG + z] = i;
}

// Warp-aggregated pair-list build: 1 ATOMG per warp per offset.
__global__ void k_pairs(const int* __restrict__ coords, int M) {
    int i    = blockIdx.x * blockDim.x + threadIdx.x;
    int lane = threadIdx.x & 31;
    bool act = (i < M) && (i < MAXM);
    int cx = 0, cy = 0, cz = 0;
    if (act) {
        cx = coords[3 * i + 0];
        cy = coords[3 * i + 1];
        cz = coords[3 * i + 2];
    }
    for (int k = 0; k < NOFF; k++) {
        int dx = k / 9 - 1, dy = (k / 3) % 3 - 1, dz = k % 3 - 1;
        int nidx = -1;
        if (act) {
            int nx = cx + dx, ny = cy + dy, nz = cz + dz;
            if (nx >= 0 && nx < DG && ny >= 0 && ny < DG && nz >= 0 && nz < DG)
                nidx = g_lookup[(nx * DG + ny) * DG + nz];
        }
        bool valid = (nidx >= 0);
        unsigned m = __ballot_sync(0xffffffffu, valid);
        if (!m) continue;
        int total  = __popc(m);
        int leader = __ffs(m) - 1;
        int base = 0;
        if (lane == leader) base = atomicAdd(&g_cnt[k], total);
        base = __shfl_sync(0xffffffffu, base, leader);
        if (valid) {
            int pos = k * MAXM + base + __popc(m & ((1u << lane) - 1));
            g_pout[pos] = i;
            g_pin [pos] = nidx;
        }
    }
}

// One kernel initializes BOTH accumulators with their biases (float4 stores).
// Mq = M*16 quads per tensor. quads [0,Mq): g_h <- b1 ; [Mq,2Mq): out <- b2.
__global__ void k_bias2(float* __restrict__ out, const float* __restrict__ b1,
                        const float* __restrict__ b2, int Mq) {
    int i = blockIdx.x * blockDim.x + threadIdx.x;
    if (i >= 2 * Mq) return;
    bool second = (i >= Mq);
    int q = second ? i - Mq : i;
    const float* b = second ? b2 : b1;
    float4* dst = second ? (float4*)out : (float4*)g_h;
    int c = (q & 15) * 4;
    dst[q] = make_float4(b[c], b[c + 1], b[c + 2], b[c + 3]);
}

__global__ void k_relu4(float4* __restrict__ x, int nquad) {
    int i = blockIdx.x * blockDim.x + threadIdx.x;
    if (i < nquad) {
        float4 v = x[i];
        v.x = fmaxf(v.x, 0.f); v.y = fmaxf(v.y, 0.f);
        v.z = fmaxf(v.z, 0.f); v.w = fmaxf(v.w, 0.f);
        x[i] = v;
    }
}

// ---------------------------------------------------------------------------
__device__ __forceinline__ void fma2(unsigned long long& d,
                                     unsigned long long a,
                                     unsigned long long b) {
    asm("fma.rn.f32x2 %0, %1, %2, %3;" : "=l"(d) : "l"(a), "l"(b), "l"(d));
}
__device__ __forceinline__ unsigned long long dup2(float s) {
    unsigned long long d;
    unsigned u = __float_as_uint(s);
    asm("mov.b64 %0, {%1, %1};" : "=l"(d) : "r"(u));
    return d;
}
__device__ __forceinline__ float lo32(unsigned long long v) {
    return __uint_as_float((unsigned)v);
}
__device__ __forceinline__ float hi32(unsigned long long v) {
    return __uint_as_float((unsigned)(v >> 32));
}
__device__ __forceinline__ void red4(float* p, float a, float b, float c, float d) {
    asm volatile("red.global.add.v4.f32 [%0], {%1, %2, %3, %4};"
                 :: "l"(p), "f"(a), "f"(b), "f"(c), "f"(d) : "memory");
}

// One block = 128 pairs of offset k, 128 threads.
// SMEM: sW [64x64] (16KB) + sGT [j=64][p=128] (32KB) = 48KB.
// Thread tile: 8 points x 8 channels as 8x4 packed f32x2 accumulators
// (pairs over channels -> W loads naturally paired, activations dup-packed).
// xin==nullptr -> g_h input; outp==nullptr -> g_h output.
__global__ void __launch_bounds__(128) k_conv(const float* xin,
                                              const float* __restrict__ W,
                                              float* outp, int relu_g) {
    extern __shared__ float sm[];
    float* sW  = sm;            // 4096 floats
    float* sGT = sm + 4096;     // 64*128 floats, j-major

    const float* x = xin  ? xin  : (const float*)g_h;
    float* out     = outp ? outp : g_h;

    int k    = blockIdx.y;
    int cnt  = g_cnt[k];
    int base = blockIdx.x * 128;
    if (base >= cnt) return;

    int tx = threadIdx.x;

    // Stage W_k
    const float4* Wk4 = (const float4*)(W + k * (NCH * NCH));
    float4* sW4 = (float4*)sW;
#pragma unroll
    for (int t = 0; t < 8; t++) sW4[tx + t * 128] = Wk4[tx + t * 128];

    // Gather one input row per thread, transposed into sGT[j][p]; optional ReLU.
    int p = tx;
    int gidx = -1;
    if (base + p < cnt) gidx = g_pin[k * MAXM + base + p];
    if (gidx >= 0) {
        const float4* row = (const float4*)(x + (size_t)gidx * NCH);
#pragma unroll
        for (int q = 0; q < 16; q++) {
            float4 v = row[q];
            if (relu_g) {
                v.x = fmaxf(v.x, 0.f); v.y = fmaxf(v.y, 0.f);
                v.z = fmaxf(v.z, 0.f); v.w = fmaxf(v.w, 0.f);
            }
            sGT[(4 * q + 0) * 128 + p] = v.x;
            sGT[(4 * q + 1) * 128 + p] = v.y;
            sGT[(4 * q + 2) * 128 + p] = v.z;
            sGT[(4 * q + 3) * 128 + p] = v.w;
        }
    } else {
#pragma unroll
        for (int j = 0; j < NCH; j++) sGT[j * 128 + p] = 0.0f;
    }
    __syncthreads();

    int cg = tx & 7;        // channels cg*8 .. cg*8+7
    int pg = tx >> 3;       // points   pg*8 .. pg*8+7

    unsigned long long acc[8][4];   // [point][channel-pair]
#pragma unroll
    for (int a = 0; a < 8; a++)
#pragma unroll
        for (int b = 0; b < 4; b++) acc[a][b] = 0ull;

    const float* gtb = sGT + pg * 8;
    const float* wb  = sW  + cg * 8;

#pragma unroll 4
    for (int j = 0; j < NCH; j++) {
        float4 a0 = *(const float4*)(gtb + j * 128);
        float4 a1 = *(const float4*)(gtb + j * 128 + 4);
        unsigned long long av[8];
        av[0] = dup2(a0.x); av[1] = dup2(a0.y);
        av[2] = dup2(a0.z); av[3] = dup2(a0.w);
        av[4] = dup2(a1.x); av[5] = dup2(a1.y);
        av[6] = dup2(a1.z); av[7] = dup2(a1.w);
        ulonglong2 b01 = *(const ulonglong2*)(wb + j * 64);
        ulonglong2 b23 = *(const ulonglong2*)(wb + j * 64 + 4);
        unsigned long long bv[4] = {b01.x, b01.y, b23.x, b23.y};
#pragma unroll
        for (int pp = 0; pp < 8; pp++)
#pragma unroll
            for (int c2 = 0; c2 < 4; c2++)
                fma2(acc[pp][c2], av[pp], bv[c2]);
    }

    // Scatter-add: 2x red.global.add.v4.f32 per point.
#pragma unroll
    for (int pp = 0; pp < 8; pp++) {
        int pairidx = base + pg * 8 + pp;
        if (pairidx < cnt) {
            int row = g_pout[k * MAXM + pairidx];
            float* o = out + (size_t)row * NCH + cg * 8;
            red4(o,     lo32(acc[pp][0]), hi32(acc[pp][0]),
                        lo32(acc[pp][1]), hi32(acc[pp][1]));
            red4(o + 4, lo32(acc[pp][2]), hi32(acc[pp][2]),
                        lo32(acc[pp][3]), hi32(acc[pp][3]));
        }
    }
}

// ---------------------------------------------------------------------------
extern "C" void kernel_launch(void* const* d_in, const int* in_sizes, int n_in,
                              void* d_out, int out_size) {
    const float* feats  = (const float*)d_in[0];
    const float* W1     = (const float*)d_in[1];
    const float* b1     = (const float*)d_in[2];
    const float* W2     = (const float*)d_in[3];
    const float* b2     = (const float*)d_in[4];
    const int*   coords = (const int*)d_in[5];
    int M = in_sizes[0] / NCH;
    float* out = (float*)d_out;

    const int smem = (4096 + NCH * 128) * (int)sizeof(float);  // 49152 B

    int vq = (DG * DG * DG) / 4;
    k_fill<<<(vq + 255) / 256, 256>>>(vq);
    k_scatter<<<(M + 255) / 256, 256>>>(coords, M);
    k_pairs<<<(M + 255) / 256, 256>>>(coords, M);

    int Mq = M * (NCH / 4);                 // quads per tensor
    k_bias2<<<(2 * Mq + 255) / 256, 256>>>(out, b1, b2, Mq);

    int tiles = (M + 127) / 128;
    dim3 cgrid(tiles, NOFF);

    // Layer 1: g_h += conv(feats, W1)   (g_h pre-initialized with b1)
    k_conv<<<cgrid, 128, smem>>>(feats, W1, nullptr, 0);
    // Layer 2: out += conv(relu(g_h), W2)  (ReLU fused into gather)
    k_conv<<<cgrid, 128, smem>>>(nullptr, W2, out, 1);
    // Final ReLU
    k_relu4<<<(Mq + 255) / 256, 256>>>((float4*)out, Mq);
}